// round 15
// baseline (speedup 1.0000x reference)
#include <cuda_runtime.h>
#include <cstdint>

#define NPTS  16384
#define SPTS  1024
#define KNN   32
#define FPS_CLUSTER 8
#define FPS_THREADS 256
#define PTS_PER_THREAD 8   // 8 CTAs * 256 thr * 8 pts = 16384
#define NFPSBLK 32
#define NQBLK   96         // 12 query clusters; 16 clusters total = single wave at 1 CTA/SM

typedef unsigned long long u64;

__device__ int g_group_idx[4*SPTS*KNN];
__device__ unsigned int g_ready[4*SPTS];
__device__ int g_qctr;

extern __shared__ float s_raw[];

__device__ __forceinline__ float sq3(float x, float y, float z) {
    return __fadd_rn(__fadd_rn(__fmul_rn(x, x), __fmul_rn(y, y)), __fmul_rn(z, z));
}
__device__ __forceinline__ u64 pk(float a, float b) {
    u64 r; asm("mov.b64 %0,{%1,%2};" : "=l"(r) : "f"(a), "f"(b)); return r;
}
__device__ __forceinline__ float2 upk(u64 v) {
    float2 r; asm("mov.b64 {%0,%1},%2;" : "=f"(r.x), "=f"(r.y) : "l"(v)); return r;
}
__device__ __forceinline__ u64 add2_(u64 a, u64 b) {
    u64 r; asm("add.rn.f32x2 %0,%1,%2;" : "=l"(r) : "l"(a), "l"(b)); return r;
}
__device__ __forceinline__ u64 mul2_(u64 a, u64 b) {
    u64 r; asm("mul.rn.f32x2 %0,%1,%2;" : "=l"(r) : "l"(a), "l"(b)); return r;
}
__device__ __forceinline__ uint32_t smem_u32(const void* p) {
    uint32_t a;
    asm("{ .reg .u64 t; cvta.to.shared.u64 t, %1; cvt.u32.u64 %0, t; }" : "=r"(a) : "l"(p));
    return a;
}
__device__ __forceinline__ uint32_t redux_max_u32(uint32_t v) {
    uint32_t r; asm("redux.sync.max.u32 %0,%1,0xffffffff;" : "=r"(r) : "r"(v)); return r;
}
__device__ __forceinline__ uint32_t redux_min_u32(uint32_t v) {
    uint32_t r; asm("redux.sync.min.u32 %0,%1,0xffffffff;" : "=r"(r) : "r"(v)); return r;
}

// ---------------------------------------------------------------- reset (flags + queue)
__global__ void reset_kernel() {
    int i = blockIdx.x * blockDim.x + threadIdx.x;
    if (i < 4 * SPTS) g_ready[i] = 0;
    if (i == 0) g_qctr = 0;
}

// ---------------------------------------------------------------- FPS body (R11 verbatim + release flag)
__device__ __forceinline__ void fps_body(const float* __restrict__ xyz,
                                         float* __restrict__ out_newxyz) {
    __shared__ u64   s_wkey[8], s_wxy[8], s_wz[8];
    __shared__ u64   s_ck[2][FPS_CLUSTER][3];
    __shared__ float s_cx, s_cy, s_cz;

    const int tid = threadIdx.x, lane = tid & 31, wid = tid >> 5;
    uint32_t rank;
    asm("mov.u32 %0, %%cluster_ctarank;" : "=r"(rank));
    const int b = blockIdx.x >> 3;
    const float* xb = xyz + (size_t)b * NPTS * 3;

    const int base = (int)rank * (NPTS / FPS_CLUSTER) + tid * PTS_PER_THREAD;
    u64 px[4], py[4], pz[4], dd[4];
#pragma unroll
    for (int j = 0; j < 4; j++) {
        int p = base + 2 * j;
        px[j] = pk(xb[3*p],   xb[3*p+3]);
        py[j] = pk(xb[3*p+1], xb[3*p+4]);
        pz[j] = pk(xb[3*p+2], xb[3*p+5]);
        dd[j] = pk(1e10f, 1e10f);
    }
    if (tid == 0) { s_cx = xb[0]; s_cy = xb[1]; s_cz = xb[2]; }

    for (int t = 0; t < SPTS; t++) {
        const int buf = t & 1;
        __syncthreads();
        float cx = s_cx, cy = s_cy, cz = s_cz;
        if (rank == 0 && tid == 0) {
            out_newxyz[(b*SPTS+t)*3+0] = cx;
            out_newxyz[(b*SPTS+t)*3+1] = cy;
            out_newxyz[(b*SPTS+t)*3+2] = cz;
            asm volatile("st.release.gpu.global.u32 [%0], %1;"
                         :: "l"(&g_ready[b*SPTS+t]), "r"(1u) : "memory");
        }
        u64 ncx = pk(-cx,-cx), ncy = pk(-cy,-cy), ncz = pk(-cz,-cz);
        float bv = -1.0f; uint32_t bp = 0;
#pragma unroll
        for (int j = 0; j < 4; j++) {
            u64 dx = add2_(px[j], ncx);
            u64 dy = add2_(py[j], ncy);
            u64 dz = add2_(pz[j], ncz);
            u64 s  = add2_(add2_(mul2_(dx,dx), mul2_(dy,dy)), mul2_(dz,dz));
            float2 sf = upk(s);
            float2 od = upk(dd[j]);
            float n0 = fminf(od.x, sf.x);
            float n1 = fminf(od.y, sf.y);
            dd[j] = pk(n0, n1);
            int p = base + 2 * j;
            if (n0 > bv) { bv = n0; bp = (uint32_t)p; }
            if (n1 > bv) { bv = n1; bp = (uint32_t)(p + 1); }
        }
        uint32_t db   = __float_as_uint(bv);
        uint32_t wmax = redux_max_u32(db);
        uint32_t cand = (db == wmax) ? bp : 0xffffffffu;
        uint32_t wmin = redux_min_u32(cand);
        if (db == wmax && bp == wmin) {
            int jj   = (int)(bp - (uint32_t)base) >> 1;
            int half = (int)(bp - (uint32_t)base) & 1;
            float vx = 0.f, vy = 0.f, vz = 0.f;
#pragma unroll
            for (int j = 0; j < 4; j++) if (j == jj) {
                float2 fx = upk(px[j]), fy = upk(py[j]), fz = upk(pz[j]);
                vx = half ? fx.y : fx.x;
                vy = half ? fy.y : fy.x;
                vz = half ? fz.y : fz.x;
            }
            s_wkey[wid] = ((u64)wmax << 32) | (u64)(uint32_t)(~wmin);
            s_wxy[wid]  = pk(vx, vy);
            s_wz[wid]   = pk(vz, 0.f);
        }
        __syncthreads();
        if (wid == 0) {
            u64 k = s_wkey[lane & 7];
#pragma unroll
            for (int off = 4; off; off >>= 1) {
                u64 o = __shfl_xor_sync(~0u, k, off);
                k = (o > k) ? o : k;
            }
            if (lane < 8) {
                int ww = 0;
#pragma unroll
                for (int w = 0; w < 8; w++) if (s_wkey[w] == k) { ww = w; break; }
                u64 cxy = s_wxy[ww], czz = s_wz[ww];
                uint32_t laddr = smem_u32(&s_ck[buf][rank][0]);
                uint32_t rad;
                asm("mapa.shared::cluster.u32 %0,%1,%2;" : "=r"(rad) : "r"(laddr), "r"(lane));
                asm volatile("st.shared::cluster.u64 [%0],%1;"    :: "r"(rad), "l"(k)   : "memory");
                asm volatile("st.shared::cluster.u64 [%0+8],%1;"  :: "r"(rad), "l"(cxy) : "memory");
                asm volatile("st.shared::cluster.u64 [%0+16],%1;" :: "r"(rad), "l"(czz) : "memory");
            }
        }
        asm volatile("barrier.cluster.arrive.aligned;" ::: "memory");
        asm volatile("barrier.cluster.wait.aligned;"   ::: "memory");
        if (wid == 0) {
            u64 k = s_ck[buf][lane & 7][0];
#pragma unroll
            for (int off = 4; off; off >>= 1) {
                u64 o = __shfl_xor_sync(~0u, k, off);
                k = (o > k) ? o : k;
            }
            if (lane == 0) {
                uint32_t widx = ~(uint32_t)k;
                int w = widx >> 11;
                float2 xy = upk(s_ck[buf][w][1]);
                float2 zz = upk(s_ck[buf][w][2]);
                s_cx = xy.x; s_cy = xy.y; s_cz = zz.x;
            }
        }
    }
}

// ---------------------------------------------------------------- query body (R11 verbatim)
__device__ __forceinline__ void query_body(const float* __restrict__ xyz,
                                           const float* __restrict__ newxyz, int cid) {
    float* sd   = s_raw;            // NPTS
    float* minv = sd + NPTS;        // 256
    int*   mini = (int*)(minv + 256);

    const int b = cid >> 10, tid = threadIdx.x;
    const float cx = newxyz[cid*3], cy = newxyz[cid*3+1], cz = newxyz[cid*3+2];
    const float cn = sq3(cx, cy, cz);
    const float* xb = xyz + (size_t)b * NPTS * 3;

    for (int p = tid; p < NPTS; p += 256) {
        float x = xb[3*p], y = xb[3*p+1], z = xb[3*p+2];
        float xn = sq3(x, y, z);
        float dot = __fadd_rn(__fadd_rn(__fmul_rn(cx, x), __fmul_rn(cy, y)),
                              __fmul_rn(cz, z));
        sd[p] = __fadd_rn(__fadd_rn(cn, __fmul_rn(-2.0f, dot)), xn);
    }
    __syncthreads();
    {
        float bv = __int_as_float(0x7f800000); int bi = 0;
        for (int i = 0; i < 64; i++) {
            int idx = tid + (i << 8);
            float v = sd[idx];
            if (v < bv) { bv = v; bi = idx; }
        }
        minv[tid] = bv; mini[tid] = bi;
    }
    __syncthreads();
    if (tid < 32) {
        const int lane = tid;
        const float INF = __int_as_float(0x7f800000);
        int* gout = g_group_idx + (size_t)cid * KNN;
        for (int sel = 0; sel < KNN; sel++) {
            float bv = INF; int bi = 0x7fffffff;
#pragma unroll
            for (int q = 0; q < 8; q++) {
                int c = lane + (q << 5);
                float v = minv[c]; int ii = mini[c];
                if (v < bv || (v == bv && ii < bi)) { bv = v; bi = ii; }
            }
#pragma unroll
            for (int off = 16; off; off >>= 1) {
                float ov = __shfl_xor_sync(~0u, bv, off);
                int   oi = __shfl_xor_sync(~0u, bi, off);
                if (ov < bv || (ov == bv && oi < bi)) { bv = ov; bi = oi; }
            }
            if (lane == 0) { gout[sel] = bi; sd[bi] = INF; }
            __syncwarp();
            int cs = bi & 255;
            float nv = INF; int ni = 0x7fffffff;
#pragma unroll
            for (int jj = 0; jj < 2; jj++) {
                int idx = cs + ((2*lane + jj) << 8);
                float v = sd[idx];
                if (v < nv || (v == nv && idx < ni)) { nv = v; ni = idx; }
            }
#pragma unroll
            for (int off = 16; off; off >>= 1) {
                float ov = __shfl_xor_sync(~0u, nv, off);
                int   oi = __shfl_xor_sync(~0u, ni, off);
                if (ov < nv || (ov == nv && oi < ni)) { nv = ov; ni = oi; }
            }
            if (lane == 0) { minv[cs] = nv; mini[cs] = ni; }
            __syncwarp();
        }
    }
}

// ---------------------------------------------------------------- fused: 32 fps CTAs + 96 persistent query CTAs
__global__ void __launch_bounds__(256, 1) __cluster_dims__(FPS_CLUSTER, 1, 1)
fused_kernel(const float* __restrict__ xyz, float* __restrict__ out_newxyz) {
    if (blockIdx.x < NFPSBLK) {
        fps_body(xyz, out_newxyz);
        return;
    }
    __shared__ int s_cid;
    for (;;) {
        if (threadIdx.x == 0) {
            int pos = atomicAdd(&g_qctr, 1);
            if (pos < 4 * SPTS) {
                unsigned int got;
                for (;;) {
                    asm volatile("ld.acquire.gpu.global.u32 %0, [%1];"
                                 : "=r"(got) : "l"(&g_ready[pos]) : "memory");
                    if (got) break;
                    __nanosleep(100);
                }
            }
            s_cid = (pos < 4 * SPTS) ? pos : -1;
        }
        __syncthreads();
        int cid = s_cid;
        if (cid < 0) break;
        query_body(xyz, out_newxyz, cid);
        __syncthreads();
    }
}

// ---------------------------------------------------------------- MLP (R11 verbatim; 67KB smem, 3 CTAs/SM)
#define FMA4(acc, a, w) \
    acc.x = fmaf(a, w.x, acc.x); acc.y = fmaf(a, w.y, acc.y); \
    acc.z = fmaf(a, w.z, acc.z); acc.w = fmaf(a, w.w, acc.w);

template<int CIN, int COUT, int LDX, int LDY>
__device__ __forceinline__ void layer_mm(const float* X, float* Y, const float* Wk,
                                         const float* sbias, int tid) {
    const int TPC = COUT / 4;
    const float4* W4 = (const float4*)Wk;
    const float4* b4 = (const float4*)sbias;
    for (int tile = tid; tile < 16 * TPC; tile += 256) {
        int r0 = (tile / TPC) * 4, c4 = tile % TPC;
        const float* x0 = X + r0 * LDX;
        const float* x1 = x0 + LDX;
        const float* x2 = x1 + LDX;
        const float* x3 = x2 + LDX;
        float4 acc0 = b4[c4], acc1 = acc0, acc2 = acc0, acc3 = acc0;
#pragma unroll 4
        for (int k4 = 0; k4 < CIN / 4; k4++) {
            float4 xv0 = ((const float4*)x0)[k4];
            float4 xv1 = ((const float4*)x1)[k4];
            float4 xv2 = ((const float4*)x2)[k4];
            float4 xv3 = ((const float4*)x3)[k4];
#pragma unroll
            for (int kk = 0; kk < 4; kk++) {
                float4 w = W4[(k4*4 + kk) * TPC + c4];
                float a0 = (&xv0.x)[kk], a1 = (&xv1.x)[kk];
                float a2 = (&xv2.x)[kk], a3 = (&xv3.x)[kk];
                FMA4(acc0, a0, w) FMA4(acc1, a1, w)
                FMA4(acc2, a2, w) FMA4(acc3, a3, w)
            }
        }
#pragma unroll
        for (int k = (CIN/4)*4; k < CIN; k++) {
            float4 w = W4[k * TPC + c4];
            float a0 = x0[k], a1 = x1[k], a2 = x2[k], a3 = x3[k];
            FMA4(acc0, a0, w) FMA4(acc1, a1, w)
            FMA4(acc2, a2, w) FMA4(acc3, a3, w)
        }
        acc0.x=fmaxf(acc0.x,0.f); acc0.y=fmaxf(acc0.y,0.f); acc0.z=fmaxf(acc0.z,0.f); acc0.w=fmaxf(acc0.w,0.f);
        acc1.x=fmaxf(acc1.x,0.f); acc1.y=fmaxf(acc1.y,0.f); acc1.z=fmaxf(acc1.z,0.f); acc1.w=fmaxf(acc1.w,0.f);
        acc2.x=fmaxf(acc2.x,0.f); acc2.y=fmaxf(acc2.y,0.f); acc2.z=fmaxf(acc2.z,0.f); acc2.w=fmaxf(acc2.w,0.f);
        acc3.x=fmaxf(acc3.x,0.f); acc3.y=fmaxf(acc3.y,0.f); acc3.z=fmaxf(acc3.z,0.f); acc3.w=fmaxf(acc3.w,0.f);
        ((float4*)(Y + (r0  ) * LDY))[c4] = acc0;
        ((float4*)(Y + (r0+1) * LDY))[c4] = acc1;
        ((float4*)(Y + (r0+2) * LDY))[c4] = acc2;
        ((float4*)(Y + (r0+3) * LDY))[c4] = acc3;
    }
}

__global__ void __launch_bounds__(256, 3)
mlp_kernel(const float* __restrict__ xyz, const float* __restrict__ points,
           const float* __restrict__ newxyz,
           const float* __restrict__ w0, const float* __restrict__ g0, const float* __restrict__ b0,
           const float* __restrict__ mm0, const float* __restrict__ mv0,
           const float* __restrict__ w1, const float* __restrict__ g1, const float* __restrict__ b1,
           const float* __restrict__ mm1, const float* __restrict__ mv1,
           const float* __restrict__ w2, const float* __restrict__ g2, const float* __restrict__ b2,
           const float* __restrict__ mm2, const float* __restrict__ mv2,
           float* __restrict__ out_np) {
    float* Xa = s_raw;              // 64*68  = 4352
    float* Xb = Xa + 64*68;         // 64*128 = 8192
    float* Wk = Xb + 64*128;        // 4352
    float* sbias  = Wk + 4352;      // 128
    float* sscale = sbias + 128;    // 128
    const int tid = threadIdx.x;

    {
        int r = tid >> 2, q = tid & 3;
        int grp = blockIdx.x * 2 + (r >> 5);
        int b = grp >> 10;
        int pidx = g_group_idx[grp * KNN + (r & 31)];
        const float4* p4 = (const float4*)(points + ((size_t)b * NPTS + pidx) * 64);
        float* xr = Xa + r * 68;
#pragma unroll
        for (int m = 0; m < 4; m++) {
            float4 v = p4[q * 4 + m];
            int cc = 3 + (q * 4 + m) * 4;
            xr[cc] = v.x; xr[cc+1] = v.y; xr[cc+2] = v.z; xr[cc+3] = v.w;
        }
        if (q == 0) {
            const float* xp = xyz + ((size_t)b * NPTS + pidx) * 3;
            const float* nx = newxyz + (size_t)grp * 3;
            xr[0] = xp[0] - nx[0]; xr[1] = xp[1] - nx[1]; xr[2] = xp[2] - nx[2];
            xr[67] = 0.f;
        }
    }
    __syncthreads();
    {
        if (tid < 64) {
            float s = g0[tid] * rsqrtf(mv0[tid] + 1e-3f);
            sscale[tid] = s;
            sbias[tid]  = b0[tid] - mm0[tid] * s;
        }
        __syncthreads();
        for (int i = tid; i < 67 * 64; i += 256)
            Wk[i] = w0[i] * sscale[i & 63];
        __syncthreads();
    }
    layer_mm<67, 64, 68, 64>(Xa, Xb, Wk, sbias, tid);
    __syncthreads();
    {
        if (tid < 64) {
            float s = g1[tid] * rsqrtf(mv1[tid] + 1e-3f);
            sscale[tid] = s;
            sbias[tid]  = b1[tid] - mm1[tid] * s;
        }
        __syncthreads();
        for (int i = tid; i < 64 * 64; i += 256)
            Wk[i] = w1[i] * sscale[i & 63];
        __syncthreads();
    }
    layer_mm<64, 64, 64, 68>(Xb, Xa, Wk, sbias, tid);
    __syncthreads();
    if (tid < 128) {
        float s = g2[tid] * rsqrtf(mv2[tid] + 1e-3f);
        sscale[tid] = s;
        sbias[tid]  = b2[tid] - mm2[tid] * s;
    }
    __syncthreads();
#pragma unroll
    for (int h = 0; h < 2; h++) {
        for (int i = tid; i < 64 * 64; i += 256) {
            int k = i >> 6, c = i & 63;
            Wk[i] = w2[k * 128 + 64 * h + c] * sscale[64 * h + c];
        }
        __syncthreads();
        layer_mm<64, 64, 68, 128>(Xa, Xb + 64 * h, Wk, sbias + 64 * h, tid);
        __syncthreads();
    }
    {
        int gl = tid >> 7, c = tid & 127;
        int grp = blockIdx.x * 2 + gl;
        float m = 0.f;
#pragma unroll 8
        for (int nb = 0; nb < 32; nb++)
            m = fmaxf(m, Xb[(gl * 32 + nb) * 128 + c]);
        out_np[(size_t)grp * 128 + c] = m;
    }
}

extern "C" void kernel_launch(void* const* d_in, const int* in_sizes, int n_in,
                              void* d_out, int out_size) {
    const float* xyz    = (const float*)d_in[0];
    const float* points = (const float*)d_in[1];
    const float* w0 = (const float*)d_in[2],  *g0 = (const float*)d_in[3],
               *b0 = (const float*)d_in[4],  *mm0 = (const float*)d_in[5], *mv0 = (const float*)d_in[6];
    const float* w1 = (const float*)d_in[7],  *g1 = (const float*)d_in[8],
               *b1 = (const float*)d_in[9],  *mm1 = (const float*)d_in[10], *mv1 = (const float*)d_in[11];
    const float* w2 = (const float*)d_in[12], *g2 = (const float*)d_in[13],
               *b2 = (const float*)d_in[14], *mm2 = (const float*)d_in[15], *mv2 = (const float*)d_in[16];
    float* out = (float*)d_out;
    float* out_newxyz = out;              // [4,1024,3]
    float* out_np     = out + 4*SPTS*3;   // [4,1024,128]

    const int SMEM_FUSED = 118784;        // 116KB -> forces 1 CTA/SM for every block
    const int SMEM_MLP   = (64*68 + 64*128 + 4352 + 256) * 4;

    cudaFuncSetAttribute(fused_kernel, cudaFuncAttributeMaxDynamicSharedMemorySize, SMEM_FUSED);
    cudaFuncSetAttribute(mlp_kernel,   cudaFuncAttributeMaxDynamicSharedMemorySize, SMEM_MLP);

    reset_kernel<<<4, 1024>>>();
    fused_kernel<<<NFPSBLK + NQBLK, 256, SMEM_FUSED>>>(xyz, out_newxyz);
    mlp_kernel<<<4*SPTS/2, 256, SMEM_MLP>>>(
        xyz, points, out_newxyz,
        w0, g0, b0, mm0, mv0, w1, g1, b1, mm1, mv1, w2, g2, b2, mm2, mv2, out_np);
}

// round 16
// speedup vs baseline: 1.5922x; 1.5922x over previous
#include <cuda_runtime.h>
#include <cstdint>

#define NPTS  16384
#define SPTS  1024
#define KNN   32
#define FPS_CLUSTER 8
#define FPS_THREADS 256
#define PTS_PER_THREAD 8   // 8 CTAs * 256 thr * 8 pts = 16384
#define NFPSBLK 32
#define NQBLK   96

typedef unsigned long long u64;

__device__ int g_group_idx[4*SPTS*KNN];
__device__ __align__(128) unsigned int g_ready_cnt[4*32];  // one flag per batch, 128B apart
__device__ int g_qctr;

extern __shared__ float s_raw[];

__device__ __forceinline__ float sq3(float x, float y, float z) {
    return __fadd_rn(__fadd_rn(__fmul_rn(x, x), __fmul_rn(y, y)), __fmul_rn(z, z));
}
__device__ __forceinline__ u64 pk(float a, float b) {
    u64 r; asm("mov.b64 %0,{%1,%2};" : "=l"(r) : "f"(a), "f"(b)); return r;
}
__device__ __forceinline__ float2 upk(u64 v) {
    float2 r; asm("mov.b64 {%0,%1},%2;" : "=f"(r.x), "=f"(r.y) : "l"(v)); return r;
}
__device__ __forceinline__ u64 add2_(u64 a, u64 b) {
    u64 r; asm("add.rn.f32x2 %0,%1,%2;" : "=l"(r) : "l"(a), "l"(b)); return r;
}
__device__ __forceinline__ u64 mul2_(u64 a, u64 b) {
    u64 r; asm("mul.rn.f32x2 %0,%1,%2;" : "=l"(r) : "l"(a), "l"(b)); return r;
}
__device__ __forceinline__ uint32_t smem_u32(const void* p) {
    uint32_t a;
    asm("{ .reg .u64 t; cvta.to.shared.u64 t, %1; cvt.u32.u64 %0, t; }" : "=r"(a) : "l"(p));
    return a;
}
__device__ __forceinline__ uint32_t redux_max_u32(uint32_t v) {
    uint32_t r; asm("redux.sync.max.u32 %0,%1,0xffffffff;" : "=r"(r) : "r"(v)); return r;
}
__device__ __forceinline__ uint32_t redux_min_u32(uint32_t v) {
    uint32_t r; asm("redux.sync.min.u32 %0,%1,0xffffffff;" : "=r"(r) : "r"(v)); return r;
}

// ---------------------------------------------------------------- reset (flags + queue)
__global__ void reset_kernel() {
    int i = threadIdx.x;
    if (i < 4 * 32) g_ready_cnt[i] = 0;
    if (i == 0) g_qctr = 0;
}

// ---------------------------------------------------------------- FPS body (R11 verbatim + amortized count flag)
__device__ __forceinline__ void fps_body(const float* __restrict__ xyz,
                                         float* __restrict__ out_newxyz) {
    __shared__ u64   s_wkey[8], s_wxy[8], s_wz[8];
    __shared__ u64   s_ck[2][FPS_CLUSTER][3];
    __shared__ float s_cx, s_cy, s_cz;

    const int tid = threadIdx.x, lane = tid & 31, wid = tid >> 5;
    uint32_t rank;
    asm("mov.u32 %0, %%cluster_ctarank;" : "=r"(rank));
    const int b = blockIdx.x >> 3;
    const float* xb = xyz + (size_t)b * NPTS * 3;

    const int base = (int)rank * (NPTS / FPS_CLUSTER) + tid * PTS_PER_THREAD;
    u64 px[4], py[4], pz[4], dd[4];
#pragma unroll
    for (int j = 0; j < 4; j++) {
        int p = base + 2 * j;
        px[j] = pk(xb[3*p],   xb[3*p+3]);
        py[j] = pk(xb[3*p+1], xb[3*p+4]);
        pz[j] = pk(xb[3*p+2], xb[3*p+5]);
        dd[j] = pk(1e10f, 1e10f);
    }
    if (tid == 0) { s_cx = xb[0]; s_cy = xb[1]; s_cz = xb[2]; }

    for (int t = 0; t < SPTS; t++) {
        const int buf = t & 1;
        __syncthreads();
        float cx = s_cx, cy = s_cy, cz = s_cz;
        if (rank == 0 && tid == 0) {
            out_newxyz[(b*SPTS+t)*3+0] = cx;
            out_newxyz[(b*SPTS+t)*3+1] = cy;
            out_newxyz[(b*SPTS+t)*3+2] = cz;
            if ((t & 15) == 15) {
                asm volatile("st.release.gpu.global.u32 [%0], %1;"
                             :: "l"(&g_ready_cnt[b*32]), "r"((unsigned int)(t + 1)) : "memory");
            }
        }
        u64 ncx = pk(-cx,-cx), ncy = pk(-cy,-cy), ncz = pk(-cz,-cz);
        float bv = -1.0f; uint32_t bp = 0;
#pragma unroll
        for (int j = 0; j < 4; j++) {
            u64 dx = add2_(px[j], ncx);
            u64 dy = add2_(py[j], ncy);
            u64 dz = add2_(pz[j], ncz);
            u64 s  = add2_(add2_(mul2_(dx,dx), mul2_(dy,dy)), mul2_(dz,dz));
            float2 sf = upk(s);
            float2 od = upk(dd[j]);
            float n0 = fminf(od.x, sf.x);
            float n1 = fminf(od.y, sf.y);
            dd[j] = pk(n0, n1);
            int p = base + 2 * j;
            if (n0 > bv) { bv = n0; bp = (uint32_t)p; }
            if (n1 > bv) { bv = n1; bp = (uint32_t)(p + 1); }
        }
        uint32_t db   = __float_as_uint(bv);
        uint32_t wmax = redux_max_u32(db);
        uint32_t cand = (db == wmax) ? bp : 0xffffffffu;
        uint32_t wmin = redux_min_u32(cand);
        if (db == wmax && bp == wmin) {
            int jj   = (int)(bp - (uint32_t)base) >> 1;
            int half = (int)(bp - (uint32_t)base) & 1;
            float vx = 0.f, vy = 0.f, vz = 0.f;
#pragma unroll
            for (int j = 0; j < 4; j++) if (j == jj) {
                float2 fx = upk(px[j]), fy = upk(py[j]), fz = upk(pz[j]);
                vx = half ? fx.y : fx.x;
                vy = half ? fy.y : fy.x;
                vz = half ? fz.y : fz.x;
            }
            s_wkey[wid] = ((u64)wmax << 32) | (u64)(uint32_t)(~wmin);
            s_wxy[wid]  = pk(vx, vy);
            s_wz[wid]   = pk(vz, 0.f);
        }
        __syncthreads();
        if (wid == 0) {
            u64 k = s_wkey[lane & 7];
#pragma unroll
            for (int off = 4; off; off >>= 1) {
                u64 o = __shfl_xor_sync(~0u, k, off);
                k = (o > k) ? o : k;
            }
            if (lane < 8) {
                int ww = 0;
#pragma unroll
                for (int w = 0; w < 8; w++) if (s_wkey[w] == k) { ww = w; break; }
                u64 cxy = s_wxy[ww], czz = s_wz[ww];
                uint32_t laddr = smem_u32(&s_ck[buf][rank][0]);
                uint32_t rad;
                asm("mapa.shared::cluster.u32 %0,%1,%2;" : "=r"(rad) : "r"(laddr), "r"(lane));
                asm volatile("st.shared::cluster.u64 [%0],%1;"    :: "r"(rad), "l"(k)   : "memory");
                asm volatile("st.shared::cluster.u64 [%0+8],%1;"  :: "r"(rad), "l"(cxy) : "memory");
                asm volatile("st.shared::cluster.u64 [%0+16],%1;" :: "r"(rad), "l"(czz) : "memory");
            }
        }
        asm volatile("barrier.cluster.arrive.aligned;" ::: "memory");
        asm volatile("barrier.cluster.wait.aligned;"   ::: "memory");
        if (wid == 0) {
            u64 k = s_ck[buf][lane & 7][0];
#pragma unroll
            for (int off = 4; off; off >>= 1) {
                u64 o = __shfl_xor_sync(~0u, k, off);
                k = (o > k) ? o : k;
            }
            if (lane == 0) {
                uint32_t widx = ~(uint32_t)k;
                int w = widx >> 11;
                float2 xy = upk(s_ck[buf][w][1]);
                float2 zz = upk(s_ck[buf][w][2]);
                s_cx = xy.x; s_cy = xy.y; s_cz = zz.x;
            }
        }
    }
}

// ---------------------------------------------------------------- query body (R11 verbatim)
__device__ __forceinline__ void query_body(const float* __restrict__ xyz,
                                           const float* __restrict__ newxyz, int cid) {
    float* sd   = s_raw;            // NPTS
    float* minv = sd + NPTS;        // 256
    int*   mini = (int*)(minv + 256);

    const int b = cid >> 10, tid = threadIdx.x;
    const float cx = newxyz[cid*3], cy = newxyz[cid*3+1], cz = newxyz[cid*3+2];
    const float cn = sq3(cx, cy, cz);
    const float* xb = xyz + (size_t)b * NPTS * 3;

    for (int p = tid; p < NPTS; p += 256) {
        float x = xb[3*p], y = xb[3*p+1], z = xb[3*p+2];
        float xn = sq3(x, y, z);
        float dot = __fadd_rn(__fadd_rn(__fmul_rn(cx, x), __fmul_rn(cy, y)),
                              __fmul_rn(cz, z));
        sd[p] = __fadd_rn(__fadd_rn(cn, __fmul_rn(-2.0f, dot)), xn);
    }
    __syncthreads();
    {
        float bv = __int_as_float(0x7f800000); int bi = 0;
        for (int i = 0; i < 64; i++) {
            int idx = tid + (i << 8);
            float v = sd[idx];
            if (v < bv) { bv = v; bi = idx; }
        }
        minv[tid] = bv; mini[tid] = bi;
    }
    __syncthreads();
    if (tid < 32) {
        const int lane = tid;
        const float INF = __int_as_float(0x7f800000);
        int* gout = g_group_idx + (size_t)cid * KNN;
        for (int sel = 0; sel < KNN; sel++) {
            float bv = INF; int bi = 0x7fffffff;
#pragma unroll
            for (int q = 0; q < 8; q++) {
                int c = lane + (q << 5);
                float v = minv[c]; int ii = mini[c];
                if (v < bv || (v == bv && ii < bi)) { bv = v; bi = ii; }
            }
#pragma unroll
            for (int off = 16; off; off >>= 1) {
                float ov = __shfl_xor_sync(~0u, bv, off);
                int   oi = __shfl_xor_sync(~0u, bi, off);
                if (ov < bv || (ov == bv && oi < bi)) { bv = ov; bi = oi; }
            }
            if (lane == 0) { gout[sel] = bi; sd[bi] = INF; }
            __syncwarp();
            int cs = bi & 255;
            float nv = INF; int ni = 0x7fffffff;
#pragma unroll
            for (int jj = 0; jj < 2; jj++) {
                int idx = cs + ((2*lane + jj) << 8);
                float v = sd[idx];
                if (v < nv || (v == nv && idx < ni)) { nv = v; ni = idx; }
            }
#pragma unroll
            for (int off = 16; off; off >>= 1) {
                float ov = __shfl_xor_sync(~0u, nv, off);
                int   oi = __shfl_xor_sync(~0u, ni, off);
                if (ov < nv || (ov == nv && oi < ni)) { nv = ov; ni = oi; }
            }
            if (lane == 0) { minv[cs] = nv; mini[cs] = ni; }
            __syncwarp();
        }
    }
}

// ---------------------------------------------------------------- fused: 32 fps CTAs + 96 worker CTAs (1 CTA/SM)
__global__ void __launch_bounds__(256, 1) __cluster_dims__(FPS_CLUSTER, 1, 1)
fused_kernel(const float* __restrict__ xyz, float* __restrict__ out_newxyz) {
    if (blockIdx.x < NFPSBLK) {
        fps_body(xyz, out_newxyz);
        return;
    }
    __shared__ int s_cid;
    for (;;) {
        if (threadIdx.x == 0) {
            int pos = atomicAdd(&g_qctr, 1);
            if (pos < 4 * SPTS) {
                int cid   = (pos & 3) * SPTS + (pos >> 2);
                int batch = cid >> 10;
                unsigned int need = (unsigned int)((cid & 1023) + 1);
                const unsigned int* fl = &g_ready_cnt[batch * 32];
                unsigned int got;
                for (;;) {
                    asm volatile("ld.relaxed.gpu.global.u32 %0, [%1];"
                                 : "=r"(got) : "l"(fl) : "memory");
                    if (got >= need) break;
                    __nanosleep(400);
                }
                asm volatile("ld.acquire.gpu.global.u32 %0, [%1];"
                             : "=r"(got) : "l"(fl) : "memory");
                s_cid = cid;
            } else {
                s_cid = -1;
            }
        }
        __syncthreads();
        int cid = s_cid;
        if (cid < 0) break;
        query_body(xyz, out_newxyz, cid);
        __syncthreads();
    }
}

// ---------------------------------------------------------------- MLP (R11 verbatim; 67KB smem, 3 CTAs/SM)
#define FMA4(acc, a, w) \
    acc.x = fmaf(a, w.x, acc.x); acc.y = fmaf(a, w.y, acc.y); \
    acc.z = fmaf(a, w.z, acc.z); acc.w = fmaf(a, w.w, acc.w);

template<int CIN, int COUT, int LDX, int LDY>
__device__ __forceinline__ void layer_mm(const float* X, float* Y, const float* Wk,
                                         const float* sbias, int tid) {
    const int TPC = COUT / 4;
    const float4* W4 = (const float4*)Wk;
    const float4* b4 = (const float4*)sbias;
    for (int tile = tid; tile < 16 * TPC; tile += 256) {
        int r0 = (tile / TPC) * 4, c4 = tile % TPC;
        const float* x0 = X + r0 * LDX;
        const float* x1 = x0 + LDX;
        const float* x2 = x1 + LDX;
        const float* x3 = x2 + LDX;
        float4 acc0 = b4[c4], acc1 = acc0, acc2 = acc0, acc3 = acc0;
#pragma unroll 4
        for (int k4 = 0; k4 < CIN / 4; k4++) {
            float4 xv0 = ((const float4*)x0)[k4];
            float4 xv1 = ((const float4*)x1)[k4];
            float4 xv2 = ((const float4*)x2)[k4];
            float4 xv3 = ((const float4*)x3)[k4];
#pragma unroll
            for (int kk = 0; kk < 4; kk++) {
                float4 w = W4[(k4*4 + kk) * TPC + c4];
                float a0 = (&xv0.x)[kk], a1 = (&xv1.x)[kk];
                float a2 = (&xv2.x)[kk], a3 = (&xv3.x)[kk];
                FMA4(acc0, a0, w) FMA4(acc1, a1, w)
                FMA4(acc2, a2, w) FMA4(acc3, a3, w)
            }
        }
#pragma unroll
        for (int k = (CIN/4)*4; k < CIN; k++) {
            float4 w = W4[k * TPC + c4];
            float a0 = x0[k], a1 = x1[k], a2 = x2[k], a3 = x3[k];
            FMA4(acc0, a0, w) FMA4(acc1, a1, w)
            FMA4(acc2, a2, w) FMA4(acc3, a3, w)
        }
        acc0.x=fmaxf(acc0.x,0.f); acc0.y=fmaxf(acc0.y,0.f); acc0.z=fmaxf(acc0.z,0.f); acc0.w=fmaxf(acc0.w,0.f);
        acc1.x=fmaxf(acc1.x,0.f); acc1.y=fmaxf(acc1.y,0.f); acc1.z=fmaxf(acc1.z,0.f); acc1.w=fmaxf(acc1.w,0.f);
        acc2.x=fmaxf(acc2.x,0.f); acc2.y=fmaxf(acc2.y,0.f); acc2.z=fmaxf(acc2.z,0.f); acc2.w=fmaxf(acc2.w,0.f);
        acc3.x=fmaxf(acc3.x,0.f); acc3.y=fmaxf(acc3.y,0.f); acc3.z=fmaxf(acc3.z,0.f); acc3.w=fmaxf(acc3.w,0.f);
        ((float4*)(Y + (r0  ) * LDY))[c4] = acc0;
        ((float4*)(Y + (r0+1) * LDY))[c4] = acc1;
        ((float4*)(Y + (r0+2) * LDY))[c4] = acc2;
        ((float4*)(Y + (r0+3) * LDY))[c4] = acc3;
    }
}

__global__ void __launch_bounds__(256, 3)
mlp_kernel(const float* __restrict__ xyz, const float* __restrict__ points,
           const float* __restrict__ newxyz,
           const float* __restrict__ w0, const float* __restrict__ g0, const float* __restrict__ b0,
           const float* __restrict__ mm0, const float* __restrict__ mv0,
           const float* __restrict__ w1, const float* __restrict__ g1, const float* __restrict__ b1,
           const float* __restrict__ mm1, const float* __restrict__ mv1,
           const float* __restrict__ w2, const float* __restrict__ g2, const float* __restrict__ b2,
           const float* __restrict__ mm2, const float* __restrict__ mv2,
           float* __restrict__ out_np) {
    float* Xa = s_raw;              // 64*68  = 4352
    float* Xb = Xa + 64*68;         // 64*128 = 8192
    float* Wk = Xb + 64*128;        // 4352
    float* sbias  = Wk + 4352;      // 128
    float* sscale = sbias + 128;    // 128
    const int tid = threadIdx.x;

    {
        int r = tid >> 2, q = tid & 3;
        int grp = blockIdx.x * 2 + (r >> 5);
        int b = grp >> 10;
        int pidx = g_group_idx[grp * KNN + (r & 31)];
        const float4* p4 = (const float4*)(points + ((size_t)b * NPTS + pidx) * 64);
        float* xr = Xa + r * 68;
#pragma unroll
        for (int m = 0; m < 4; m++) {
            float4 v = p4[q * 4 + m];
            int cc = 3 + (q * 4 + m) * 4;
            xr[cc] = v.x; xr[cc+1] = v.y; xr[cc+2] = v.z; xr[cc+3] = v.w;
        }
        if (q == 0) {
            const float* xp = xyz + ((size_t)b * NPTS + pidx) * 3;
            const float* nx = newxyz + (size_t)grp * 3;
            xr[0] = xp[0] - nx[0]; xr[1] = xp[1] - nx[1]; xr[2] = xp[2] - nx[2];
            xr[67] = 0.f;
        }
    }
    __syncthreads();
    {
        if (tid < 64) {
            float s = g0[tid] * rsqrtf(mv0[tid] + 1e-3f);
            sscale[tid] = s;
            sbias[tid]  = b0[tid] - mm0[tid] * s;
        }
        __syncthreads();
        for (int i = tid; i < 67 * 64; i += 256)
            Wk[i] = w0[i] * sscale[i & 63];
        __syncthreads();
    }
    layer_mm<67, 64, 68, 64>(Xa, Xb, Wk, sbias, tid);
    __syncthreads();
    {
        if (tid < 64) {
            float s = g1[tid] * rsqrtf(mv1[tid] + 1e-3f);
            sscale[tid] = s;
            sbias[tid]  = b1[tid] - mm1[tid] * s;
        }
        __syncthreads();
        for (int i = tid; i < 64 * 64; i += 256)
            Wk[i] = w1[i] * sscale[i & 63];
        __syncthreads();
    }
    layer_mm<64, 64, 64, 68>(Xb, Xa, Wk, sbias, tid);
    __syncthreads();
    if (tid < 128) {
        float s = g2[tid] * rsqrtf(mv2[tid] + 1e-3f);
        sscale[tid] = s;
        sbias[tid]  = b2[tid] - mm2[tid] * s;
    }
    __syncthreads();
#pragma unroll
    for (int h = 0; h < 2; h++) {
        for (int i = tid; i < 64 * 64; i += 256) {
            int k = i >> 6, c = i & 63;
            Wk[i] = w2[k * 128 + 64 * h + c] * sscale[64 * h + c];
        }
        __syncthreads();
        layer_mm<64, 64, 68, 128>(Xa, Xb + 64 * h, Wk, sbias + 64 * h, tid);
        __syncthreads();
    }
    {
        int gl = tid >> 7, c = tid & 127;
        int grp = blockIdx.x * 2 + gl;
        float m = 0.f;
#pragma unroll 8
        for (int nb = 0; nb < 32; nb++)
            m = fmaxf(m, Xb[(gl * 32 + nb) * 128 + c]);
        out_np[(size_t)grp * 128 + c] = m;
    }
}

extern "C" void kernel_launch(void* const* d_in, const int* in_sizes, int n_in,
                              void* d_out, int out_size) {
    const float* xyz    = (const float*)d_in[0];
    const float* points = (const float*)d_in[1];
    const float* w0 = (const float*)d_in[2],  *g0 = (const float*)d_in[3],
               *b0 = (const float*)d_in[4],  *mm0 = (const float*)d_in[5], *mv0 = (const float*)d_in[6];
    const float* w1 = (const float*)d_in[7],  *g1 = (const float*)d_in[8],
               *b1 = (const float*)d_in[9],  *mm1 = (const float*)d_in[10], *mv1 = (const float*)d_in[11];
    const float* w2 = (const float*)d_in[12], *g2 = (const float*)d_in[13],
               *b2 = (const float*)d_in[14], *mm2 = (const float*)d_in[15], *mv2 = (const float*)d_in[16];
    float* out = (float*)d_out;
    float* out_newxyz = out;              // [4,1024,3]
    float* out_np     = out + 4*SPTS*3;   // [4,1024,128]

    const int SMEM_FUSED = 118784;        // 116KB -> 1 CTA/SM: fps SMs host nothing else
    const int SMEM_MLP   = (64*68 + 64*128 + 4352 + 256) * 4;

    cudaFuncSetAttribute(fused_kernel, cudaFuncAttributeMaxDynamicSharedMemorySize, SMEM_FUSED);
    cudaFuncSetAttribute(mlp_kernel,   cudaFuncAttributeMaxDynamicSharedMemorySize, SMEM_MLP);

    reset_kernel<<<1, 256>>>();
    fused_kernel<<<NFPSBLK + NQBLK, 256, SMEM_FUSED>>>(xyz, out_newxyz);
    mlp_kernel<<<4*SPTS/2, 256, SMEM_MLP>>>(
        xyz, points, out_newxyz,
        w0, g0, b0, mm0, mv0, w1, g1, b1, mm1, mv1, w2, g2, b2, mm2, mv2, out_np);
}